// round 15
// baseline (speedup 1.0000x reference)
#include <cuda_runtime.h>
#include <cuda_fp16.h>
#include <cstdint>

#define K_DIM 4096
#define N_DIM 4096
#define M_DIM 8192

// Static scratch (allocation-free rule)
__device__ __half g_X[(size_t)M_DIM * K_DIM];    // fp16 activations [M,K]
__device__ __half g_Wt[(size_t)N_DIM * K_DIM];   // fp16 dequantized weight, TRANSPOSED [N,K]

// ---------------------------------------------------------------------------
// Fused prep: activation fp32->fp16 convert AND GPTQ 4-bit dequant.
// Dequant is tiled through shared memory so the transposed g_Wt store is
// coalesced (512B-contiguous per warp) instead of 8KB-strided scatter.
// ---------------------------------------------------------------------------
constexpr int CVT_BLOCKS = (int)((size_t)M_DIM * K_DIM / 8 / 256);   // 16384
constexpr int DQ_KB_T    = 32;    // kb per tile (k range 256)
constexpr int DQ_N_T     = 64;    // n per tile
constexpr int DQ_BLOCKS  = (K_DIM / 8 / DQ_KB_T) * (N_DIM / DQ_N_T); // 16*64=1024

__global__ void prep_kernel(const float* __restrict__ x,
                            const int* __restrict__ qweight,
                            const int* __restrict__ qzeros,
                            const float* __restrict__ scales) {
    __shared__ uint4 sm[DQ_N_T * (DQ_KB_T + 1)];   // 64 x 33 uint4 = 33,792 B

    if (blockIdx.x < CVT_BLOCKS) {
        size_t i = ((size_t)blockIdx.x * 256 + threadIdx.x) * 8;
        float4 a = *reinterpret_cast<const float4*>(x + i);
        float4 b = *reinterpret_cast<const float4*>(x + i + 4);
        __half h[8];
        h[0] = __float2half(a.x); h[1] = __float2half(a.y);
        h[2] = __float2half(a.z); h[3] = __float2half(a.w);
        h[4] = __float2half(b.x); h[5] = __float2half(b.y);
        h[6] = __float2half(b.z); h[7] = __float2half(b.w);
        *reinterpret_cast<uint4*>(g_X + i) = *reinterpret_cast<uint4*>(h);
    } else {
        int b2  = blockIdx.x - CVT_BLOCKS;
        int kb0 = (b2 % (K_DIM / 8 / DQ_KB_T)) * DQ_KB_T;
        int n0  = (b2 / (K_DIM / 8 / DQ_KB_T)) * DQ_N_T;
        int tid = threadIdx.x;

        // read qweight coalesced along n; dequant; stash transposed in smem
#pragma unroll
        for (int i = 0; i < 8; i++) {
            int id = tid + i * 256;              // 2048 words
            int r  = id >> 6;                    // kb offset 0..31
            int c  = id & 63;                    // n offset 0..63
            int kb = kb0 + r, n = n0 + c;
            unsigned int q = (unsigned int)qweight[(size_t)kb * N_DIM + n];
            int g = kb >> 4;                     // GROUP=128: g_idx[k]=k/128
            unsigned int zw = (unsigned int)qzeros[(size_t)g * (N_DIM / 8) + (n >> 3)];
            int z = (int)((zw >> ((n & 7) * 4)) & 0xF);
            float s = scales[(size_t)g * N_DIM + n];
            __half h[8];
#pragma unroll
            for (int j = 0; j < 8; j++) {
                int w = (int)((q >> (4 * j)) & 0xF) - z - 1;
                h[j] = __float2half((float)w * s);
            }
            sm[c * (DQ_KB_T + 1) + r] = *reinterpret_cast<uint4*>(h);
        }
        __syncthreads();

        // write g_Wt coalesced: each warp emits one n-row's 512B run
#pragma unroll
        for (int i = 0; i < 8; i++) {
            int id  = tid + i * 256;             // 2048 uint4
            int row = id >> 5;                   // n offset 0..63
            int rr  = id & 31;                   // kb offset 0..31
            uint4 v = sm[row * (DQ_KB_T + 1) + rr];
            *reinterpret_cast<uint4*>(
                g_Wt + (size_t)(n0 + row) * K_DIM + (kb0 + rr) * 8) = v;
        }
    }
}

// ---------------------------------------------------------------------------
// Persistent warp-specialized mma.sync GEMM  out[M,N] = X * Wt^T + bias
// 128x128x64 tile, 3 stages, SW128 swizzle, R9 inner loop verbatim.
// grid = 296 persistent CTAs, static round-robin over the 2048 tiles:
// loaders prefetch the next tile while consumers run the epilogue.
// ---------------------------------------------------------------------------
constexpr int BK      = 64;
constexpr int NSTG    = 3;
constexpr int KT      = K_DIM / BK;           // 64
constexpr int A_TILE  = 128 * BK * 2;         // 16 KB
constexpr int STAGE_B = 2 * A_TILE;           // 32 KB (A + B)
constexpr int OFF_TILES = 1024;
constexpr int SMEM_TOTAL = OFF_TILES + NSTG * STAGE_B;   // 99,328 B

constexpr int N_TILES_X = N_DIM / 128;        // 32
constexpr int N_TILES   = (M_DIM / 128) * N_TILES_X;     // 2048
constexpr int GRID      = 296;                // 2 per SM

__device__ __forceinline__ uint32_t sw128(uint32_t off) {
    return off ^ ((off >> 3) & 0x70);
}

__device__ __forceinline__ uint32_t smem_u32(const void* p) {
    uint32_t a;
    asm("{ .reg .u64 t; cvta.to.shared.u64 t, %1; cvt.u32.u64 %0, t; }" : "=r"(a) : "l"(p));
    return a;
}

__device__ __forceinline__ void cp16(uint32_t saddr, const void* g) {
    asm volatile("cp.async.cg.shared.global [%0], [%1], 16;" :: "r"(saddr), "l"(g));
}

__device__ __forceinline__ void mbar_init(uint32_t m, uint32_t cnt) {
    asm volatile("mbarrier.init.shared.b64 [%0], %1;" :: "r"(m), "r"(cnt) : "memory");
}

__device__ __forceinline__ void mbar_arrive(uint32_t m) {
    asm volatile("mbarrier.arrive.shared.b64 _, [%0];" :: "r"(m) : "memory");
}

__device__ __forceinline__ void cpasync_mbar_arrive_noinc(uint32_t m) {
    asm volatile("cp.async.mbarrier.arrive.noinc.shared.b64 [%0];" :: "r"(m) : "memory");
}

__device__ __forceinline__ void wait_parity(uint32_t m, uint32_t phase) {
    asm volatile(
        "{\n\t.reg .pred P;\n\t"
        "WL_%=:\n\t"
        "mbarrier.try_wait.parity.shared.b64 P, [%0], %1;\n\t"
        "@P bra.uni WD_%=;\n\t"
        "bra.uni WL_%=;\n\t"
        "WD_%=:\n\t}"
        :: "r"(m), "r"(phase) : "memory");
}

__device__ __forceinline__ void ldsm4(uint32_t (&r)[4], uint32_t addr) {
    asm volatile("ldmatrix.sync.aligned.m8n8.x4.shared.b16 {%0,%1,%2,%3}, [%4];"
                 : "=r"(r[0]), "=r"(r[1]), "=r"(r[2]), "=r"(r[3]) : "r"(addr));
}

__device__ __forceinline__ void mma16816(float (&c)[4], const uint32_t (&a)[4],
                                         uint32_t b0, uint32_t b1) {
    asm volatile(
        "mma.sync.aligned.m16n8k16.row.col.f32.f16.f16.f32 "
        "{%0,%1,%2,%3}, {%4,%5,%6,%7}, {%8,%9}, {%0,%1,%2,%3};"
        : "+f"(c[0]), "+f"(c[1]), "+f"(c[2]), "+f"(c[3])
        : "r"(a[0]), "r"(a[1]), "r"(a[2]), "r"(a[3]), "r"(b0), "r"(b1));
}

__global__ __launch_bounds__(320, 2) void gemm_mma(const float* __restrict__ bias,
                                                   float* __restrict__ out) {
    extern __shared__ __align__(1024) char smem[];
    const uint32_t sb = smem_u32(smem);
    const int tid  = threadIdx.x;
    const int warp = tid >> 5;
    const int lane = tid & 31;

    const uint32_t fullB  = sb;          // 3 x 8B
    const uint32_t emptyB = sb + 64;     // 3 x 8B
    const uint32_t tiles  = sb + OFF_TILES;

    if (tid == 0) {
#pragma unroll
        for (int s = 0; s < NSTG; s++) {
            mbar_init(fullB  + s * 8, 64);   // 64 loader threads, noinc deferred arrive
            mbar_init(emptyB + s * 8, 8);    // 8 consumer warps (lane 0)
        }
    }
    __syncthreads();

    if (warp >= 8) {
        // ======================= LOADERS (warps 8-9) =======================
        const int lt = tid - 256;            // 0..63
        int it = 0;
        for (int tile = blockIdx.x; tile < N_TILES; tile += GRID) {
            const int n0 = (tile % N_TILES_X) * 128;
            const int m0 = (tile / N_TILES_X) * 128;
            for (int kt = 0; kt < KT; kt++, it++) {
                const int s = it % NSTG;
                if (it >= NSTG) wait_parity(emptyB + s * 8, (uint32_t)((it / NSTG - 1) & 1));
                const uint32_t base = tiles + s * STAGE_B;
                const int k0 = kt * BK;
#pragma unroll
                for (int i = 0; i < 32; i++) {
                    int idx = lt + i * 64;               // 0..2047
                    int row = (idx >> 3) & 127;
                    int ck  = idx & 7;
                    uint32_t off = sw128((uint32_t)(row * 128 + ck * 16));
                    if (idx < 1024) {
                        cp16(base + off, g_X + (size_t)(m0 + row) * K_DIM + k0 + ck * 8);
                    } else {
                        cp16(base + A_TILE + off,
                             g_Wt + (size_t)(n0 + row) * K_DIM + k0 + ck * 8);
                    }
                }
                cpasync_mbar_arrive_noinc(fullB + s * 8);
            }
        }
        return;
    }

    // ======================= CONSUMERS (warps 0-7) =========================
    const int wm = warp & 3;     // 4 warp-rows of 32
    const int wn = warp >> 2;    // 2 warp-cols of 64

    const int r16 = lane & 15;
    const int h   = lane >> 4;
    const int s7  = r16 & 7;
    const uint32_t aBase = (uint32_t)((wm * 32 + r16) * 128);
    const uint32_t bBase = (uint32_t)((wn * 64 + r16) * 128);
    uint32_t koff[4];
#pragma unroll
    for (int ks = 0; ks < 4; ks++) koff[ks] = (uint32_t)(((ks * 2 + h) ^ s7) * 16);

    int it = 0;
    for (int tile = blockIdx.x; tile < N_TILES; tile += GRID) {
        const int n0 = (tile % N_TILES_X) * 128;
        const int m0 = (tile / N_TILES_X) * 128;

        float acc[2][8][4];
#pragma unroll
        for (int mt = 0; mt < 2; mt++)
#pragma unroll
            for (int nt = 0; nt < 8; nt++)
#pragma unroll
                for (int e = 0; e < 4; e++) acc[mt][nt][e] = 0.0f;

        for (int kt = 0; kt < KT; kt++, it++) {
            const int s = it % NSTG;
            wait_parity(fullB + s * 8, (uint32_t)((it / NSTG) & 1));

            const uint32_t sA = tiles + s * STAGE_B + aBase;
            const uint32_t sB = tiles + s * STAGE_B + A_TILE + bBase;
#pragma unroll
            for (int ks = 0; ks < 4; ks++) {
                uint32_t a[2][4], b[4][4];
#pragma unroll
                for (int mt = 0; mt < 2; mt++) ldsm4(a[mt], sA + mt * 2048 + koff[ks]);
#pragma unroll
                for (int nt = 0; nt < 4; nt++) ldsm4(b[nt], sB + nt * 2048 + koff[ks]);
#pragma unroll
                for (int mt = 0; mt < 2; mt++)
#pragma unroll
                    for (int nt = 0; nt < 4; nt++) {
                        mma16816(acc[mt][nt * 2 + 0], a[mt], b[nt][0], b[nt][2]);
                        mma16816(acc[mt][nt * 2 + 1], a[mt], b[nt][1], b[nt][3]);
                    }
            }
            if (lane == 0) mbar_arrive(emptyB + s * 8);
        }

        // ---- epilogue (overlaps with loaders prefetching the next tile) ----
#pragma unroll
        for (int mt = 0; mt < 2; mt++)
#pragma unroll
            for (int nt = 0; nt < 8; nt++) {
                int r0 = m0 + wm * 32 + mt * 16 + (lane >> 2);
                int c0 = n0 + wn * 64 + nt * 8 + (lane & 3) * 2;
                float bx = bias[c0], by = bias[c0 + 1];
                float2 v0 = { __half2float(__float2half(acc[mt][nt][0] + bx)),
                              __half2float(__float2half(acc[mt][nt][1] + by)) };
                *reinterpret_cast<float2*>(out + (size_t)r0 * N_DIM + c0) = v0;
                float2 v1 = { __half2float(__float2half(acc[mt][nt][2] + bx)),
                              __half2float(__float2half(acc[mt][nt][3] + by)) };
                *reinterpret_cast<float2*>(out + (size_t)(r0 + 8) * N_DIM + c0) = v1;
            }
    }
}

// ---------------------------------------------------------------------------
// Entry point. Inputs: x, qweight, qzeros, scales, g_idx, bias (fp16 as fp32)
// ---------------------------------------------------------------------------
extern "C" void kernel_launch(void* const* d_in, const int* in_sizes, int n_in,
                              void* d_out, int out_size) {
    const float* x       = (const float*)d_in[0];
    const int*   qweight = (const int*)  d_in[1];
    const int*   qzeros  = (const int*)  d_in[2];
    const float* scales  = (const float*)d_in[3];
    const float* bias    = (const float*)d_in[5];
    float*       out     = (float*)      d_out;
    (void)in_sizes; (void)n_in; (void)out_size;

    prep_kernel<<<CVT_BLOCKS + DQ_BLOCKS, 256>>>(x, qweight, qzeros, scales);

    static bool attr_set = false;
    if (!attr_set) {
        cudaFuncSetAttribute(gemm_mma, cudaFuncAttributeMaxDynamicSharedMemorySize, SMEM_TOTAL);
        attr_set = true;
    }
    gemm_mma<<<GRID, 320, SMEM_TOTAL>>>(bias, out);
}

// round 16
// speedup vs baseline: 1.0705x; 1.0705x over previous
#include <cuda_runtime.h>
#include <cuda_fp16.h>
#include <cstdint>

#define K_DIM 4096
#define N_DIM 4096
#define M_DIM 8192

// Static scratch (allocation-free rule)
__device__ __half g_X[(size_t)M_DIM * K_DIM];    // fp16 activations [M,K]
__device__ __half g_Wt[(size_t)N_DIM * K_DIM];   // fp16 dequantized weight, TRANSPOSED [N,K]

// ---------------------------------------------------------------------------
// Fused prep: activation fp32->fp16 convert AND GPTQ 4-bit dequant.
// Dequant is tiled through shared memory so the transposed g_Wt store is
// coalesced (512B-contiguous runs) instead of an 8KB-strided scatter.
// (Measured: non-GEMM time 44.9 -> 37.5 us vs the scattered version.)
// ---------------------------------------------------------------------------
constexpr int CVT_BLOCKS = (int)((size_t)M_DIM * K_DIM / 8 / 256);   // 16384
constexpr int DQ_KB_T    = 32;    // kb per tile (k range 256)
constexpr int DQ_N_T     = 64;    // n per tile
constexpr int DQ_BLOCKS  = (K_DIM / 8 / DQ_KB_T) * (N_DIM / DQ_N_T); // 1024

__global__ void prep_kernel(const float* __restrict__ x,
                            const int* __restrict__ qweight,
                            const int* __restrict__ qzeros,
                            const float* __restrict__ scales) {
    __shared__ uint4 sm[DQ_N_T * (DQ_KB_T + 1)];   // 64 x 33 uint4

    if (blockIdx.x < CVT_BLOCKS) {
        size_t i = ((size_t)blockIdx.x * 256 + threadIdx.x) * 8;
        float4 a = *reinterpret_cast<const float4*>(x + i);
        float4 b = *reinterpret_cast<const float4*>(x + i + 4);
        __half h[8];
        h[0] = __float2half(a.x); h[1] = __float2half(a.y);
        h[2] = __float2half(a.z); h[3] = __float2half(a.w);
        h[4] = __float2half(b.x); h[5] = __float2half(b.y);
        h[6] = __float2half(b.z); h[7] = __float2half(b.w);
        *reinterpret_cast<uint4*>(g_X + i) = *reinterpret_cast<uint4*>(h);
    } else {
        int b2  = blockIdx.x - CVT_BLOCKS;
        int kb0 = (b2 % (K_DIM / 8 / DQ_KB_T)) * DQ_KB_T;
        int n0  = (b2 / (K_DIM / 8 / DQ_KB_T)) * DQ_N_T;
        int tid = threadIdx.x;

        // read qweight coalesced along n; dequant; stash transposed in smem
#pragma unroll
        for (int i = 0; i < 8; i++) {
            int id = tid + i * 256;              // 2048 words
            int r  = id >> 6;                    // kb offset 0..31
            int c  = id & 63;                    // n offset 0..63
            int kb = kb0 + r, n = n0 + c;
            unsigned int q = (unsigned int)qweight[(size_t)kb * N_DIM + n];
            int g = kb >> 4;                     // GROUP=128: g_idx[k]=k/128
            unsigned int zw = (unsigned int)qzeros[(size_t)g * (N_DIM / 8) + (n >> 3)];
            int z = (int)((zw >> ((n & 7) * 4)) & 0xF);
            float s = scales[(size_t)g * N_DIM + n];
            __half h[8];
#pragma unroll
            for (int j = 0; j < 8; j++) {
                int w = (int)((q >> (4 * j)) & 0xF) - z - 1;
                h[j] = __float2half((float)w * s);
            }
            sm[c * (DQ_KB_T + 1) + r] = *reinterpret_cast<uint4*>(h);
        }
        __syncthreads();

        // write g_Wt coalesced: 512B-contiguous runs per warp
#pragma unroll
        for (int i = 0; i < 8; i++) {
            int id  = tid + i * 256;             // 2048 uint4
            int row = id >> 5;                   // n offset 0..63
            int rr  = id & 31;                   // kb offset 0..31
            uint4 v = sm[row * (DQ_KB_T + 1) + rr];
            *reinterpret_cast<uint4*>(
                g_Wt + (size_t)(n0 + row) * K_DIM + (kb0 + rr) * 8) = v;
        }
    }
}

// ---------------------------------------------------------------------------
// Warp-specialized mma.sync GEMM  out[M,N] = X * Wt^T + bias  (R9 verbatim —
// the measured optimum: 685us GEMM, tensor 66.2%)
// 128x128x64 tile, 3 stages, SW128 swizzle. 8 consumer warps (32x64) +
// 2 loader warps (cp.async both operands), mbarrier full/empty pipeline.
// ---------------------------------------------------------------------------
constexpr int BK      = 64;
constexpr int NSTG    = 3;
constexpr int KT      = K_DIM / BK;           // 64
constexpr int A_TILE  = 128 * BK * 2;         // 16 KB
constexpr int STAGE_B = 2 * A_TILE;           // 32 KB (A + B)
constexpr int OFF_TILES = 1024;
constexpr int SMEM_TOTAL = OFF_TILES + NSTG * STAGE_B;   // 99,328 B

__device__ __forceinline__ uint32_t sw128(uint32_t off) {
    return off ^ ((off >> 3) & 0x70);
}

__device__ __forceinline__ uint32_t smem_u32(const void* p) {
    uint32_t a;
    asm("{ .reg .u64 t; cvta.to.shared.u64 t, %1; cvt.u32.u64 %0, t; }" : "=r"(a) : "l"(p));
    return a;
}

__device__ __forceinline__ void cp16(uint32_t saddr, const void* g) {
    asm volatile("cp.async.cg.shared.global [%0], [%1], 16;" :: "r"(saddr), "l"(g));
}

__device__ __forceinline__ void mbar_init(uint32_t m, uint32_t cnt) {
    asm volatile("mbarrier.init.shared.b64 [%0], %1;" :: "r"(m), "r"(cnt) : "memory");
}

__device__ __forceinline__ void mbar_arrive(uint32_t m) {
    asm volatile("mbarrier.arrive.shared.b64 _, [%0];" :: "r"(m) : "memory");
}

__device__ __forceinline__ void cpasync_mbar_arrive_noinc(uint32_t m) {
    asm volatile("cp.async.mbarrier.arrive.noinc.shared.b64 [%0];" :: "r"(m) : "memory");
}

__device__ __forceinline__ void wait_parity(uint32_t m, uint32_t phase) {
    asm volatile(
        "{\n\t.reg .pred P;\n\t"
        "WL_%=:\n\t"
        "mbarrier.try_wait.parity.shared.b64 P, [%0], %1;\n\t"
        "@P bra.uni WD_%=;\n\t"
        "bra.uni WL_%=;\n\t"
        "WD_%=:\n\t}"
        :: "r"(m), "r"(phase) : "memory");
}

__device__ __forceinline__ void ldsm4(uint32_t (&r)[4], uint32_t addr) {
    asm volatile("ldmatrix.sync.aligned.m8n8.x4.shared.b16 {%0,%1,%2,%3}, [%4];"
                 : "=r"(r[0]), "=r"(r[1]), "=r"(r[2]), "=r"(r[3]) : "r"(addr));
}

__device__ __forceinline__ void mma16816(float (&c)[4], const uint32_t (&a)[4],
                                         uint32_t b0, uint32_t b1) {
    asm volatile(
        "mma.sync.aligned.m16n8k16.row.col.f32.f16.f16.f32 "
        "{%0,%1,%2,%3}, {%4,%5,%6,%7}, {%8,%9}, {%0,%1,%2,%3};"
        : "+f"(c[0]), "+f"(c[1]), "+f"(c[2]), "+f"(c[3])
        : "r"(a[0]), "r"(a[1]), "r"(a[2]), "r"(a[3]), "r"(b0), "r"(b1));
}

__global__ __launch_bounds__(320, 2) void gemm_mma(const float* __restrict__ bias,
                                                   float* __restrict__ out) {
    extern __shared__ __align__(1024) char smem[];
    const uint32_t sb = smem_u32(smem);
    const int tid  = threadIdx.x;
    const int warp = tid >> 5;
    const int lane = tid & 31;
    const int m0   = blockIdx.y * 128;
    const int n0   = blockIdx.x * 128;

    const uint32_t fullB  = sb;          // 3 x 8B
    const uint32_t emptyB = sb + 64;     // 3 x 8B
    const uint32_t tiles  = sb + OFF_TILES;

    if (tid == 0) {
#pragma unroll
        for (int s = 0; s < NSTG; s++) {
            mbar_init(fullB  + s * 8, 64);   // 64 loader threads, noinc deferred arrive
            mbar_init(emptyB + s * 8, 8);    // 8 consumer warps (lane 0)
        }
    }
    __syncthreads();

    if (warp >= 8) {
        // ======================= LOADERS (warps 8-9) =======================
        const int lt = tid - 256;            // 0..63
        for (int j = 0; j < KT; j++) {
            const int s = j % NSTG;
            if (j >= NSTG) wait_parity(emptyB + s * 8, (uint32_t)((j / NSTG - 1) & 1));
            const uint32_t base = tiles + s * STAGE_B;
            const int k0 = j * BK;
#pragma unroll
            for (int i = 0; i < 32; i++) {
                int idx = lt + i * 64;               // 0..2047
                int row = (idx >> 3) & 127;
                int ck  = idx & 7;
                uint32_t off = sw128((uint32_t)(row * 128 + ck * 16));
                if (idx < 1024) {
                    cp16(base + off, g_X + (size_t)(m0 + row) * K_DIM + k0 + ck * 8);
                } else {
                    cp16(base + A_TILE + off, g_Wt + (size_t)(n0 + row) * K_DIM + k0 + ck * 8);
                }
            }
            cpasync_mbar_arrive_noinc(fullB + s * 8);  // arrive when this thread's cps land
        }
        return;
    }

    // ======================= CONSUMERS (warps 0-7) =========================
    const int wm = warp & 3;     // 4 warp-rows of 32
    const int wn = warp >> 2;    // 2 warp-cols of 64

    float acc[2][8][4];
#pragma unroll
    for (int mt = 0; mt < 2; mt++)
#pragma unroll
        for (int nt = 0; nt < 8; nt++)
#pragma unroll
            for (int e = 0; e < 4; e++) acc[mt][nt][e] = 0.0f;

    const int r16 = lane & 15;
    const int h   = lane >> 4;
    const int s7  = r16 & 7;
    const uint32_t aBase = (uint32_t)((wm * 32 + r16) * 128);
    const uint32_t bBase = (uint32_t)((wn * 64 + r16) * 128);
    uint32_t koff[4];
#pragma unroll
    for (int ks = 0; ks < 4; ks++) koff[ks] = (uint32_t)(((ks * 2 + h) ^ s7) * 16);

    for (int kt = 0; kt < KT; kt++) {
        const int s = kt % NSTG;
        wait_parity(fullB + s * 8, (uint32_t)((kt / NSTG) & 1));

        const uint32_t sA = tiles + s * STAGE_B + aBase;
        const uint32_t sB = tiles + s * STAGE_B + A_TILE + bBase;
#pragma unroll
        for (int ks = 0; ks < 4; ks++) {
            uint32_t a[2][4], b[4][4];
#pragma unroll
            for (int mt = 0; mt < 2; mt++) ldsm4(a[mt], sA + mt * 2048 + koff[ks]);
#pragma unroll
            for (int nt = 0; nt < 4; nt++) ldsm4(b[nt], sB + nt * 2048 + koff[ks]);
#pragma unroll
            for (int mt = 0; mt < 2; mt++)
#pragma unroll
                for (int nt = 0; nt < 4; nt++) {
                    mma16816(acc[mt][nt * 2 + 0], a[mt], b[nt][0], b[nt][2]);
                    mma16816(acc[mt][nt * 2 + 1], a[mt], b[nt][1], b[nt][3]);
                }
        }
        if (lane == 0) mbar_arrive(emptyB + s * 8);
    }

    // ------- epilogue: regs -> global, + bias, single fp16 rounding -------
#pragma unroll
    for (int mt = 0; mt < 2; mt++)
#pragma unroll
        for (int nt = 0; nt < 8; nt++) {
            int r0 = m0 + wm * 32 + mt * 16 + (lane >> 2);
            int c0 = n0 + wn * 64 + nt * 8 + (lane & 3) * 2;
            float bx = bias[c0], by = bias[c0 + 1];
            float2 v0 = { __half2float(__float2half(acc[mt][nt][0] + bx)),
                          __half2float(__float2half(acc[mt][nt][1] + by)) };
            *reinterpret_cast<float2*>(out + (size_t)r0 * N_DIM + c0) = v0;
            float2 v1 = { __half2float(__float2half(acc[mt][nt][2] + bx)),
                          __half2float(__float2half(acc[mt][nt][3] + by)) };
            *reinterpret_cast<float2*>(out + (size_t)(r0 + 8) * N_DIM + c0) = v1;
        }
}

// ---------------------------------------------------------------------------
// Entry point. Inputs: x, qweight, qzeros, scales, g_idx, bias (fp16 as fp32)
// ---------------------------------------------------------------------------
extern "C" void kernel_launch(void* const* d_in, const int* in_sizes, int n_in,
                              void* d_out, int out_size) {
    const float* x       = (const float*)d_in[0];
    const int*   qweight = (const int*)  d_in[1];
    const int*   qzeros  = (const int*)  d_in[2];
    const float* scales  = (const float*)d_in[3];
    const float* bias    = (const float*)d_in[5];
    float*       out     = (float*)      d_out;
    (void)in_sizes; (void)n_in; (void)out_size;

    prep_kernel<<<CVT_BLOCKS + DQ_BLOCKS, 256>>>(x, qweight, qzeros, scales);

    static bool attr_set = false;
    if (!attr_set) {
        cudaFuncSetAttribute(gemm_mma, cudaFuncAttributeMaxDynamicSharedMemorySize, SMEM_TOTAL);
        attr_set = true;
    }
    dim3 grid(N_DIM / 128, M_DIM / 128);   // 32 x 64 = 2048 CTAs
    gemm_mma<<<grid, 320, SMEM_TOTAL>>>(bias, out);
}